// round 3
// baseline (speedup 1.0000x reference)
#include <cuda_runtime.h>

#define NB 512
#define NT 1024
#define NK 48
#define SSTART 46
#define SEND 47
#define NEGV (-10000.0f)
#define L2E 1.4426950408889634f
#define LN2F 0.6931471805599453f

// dyn smem: bp[NT*NK] u8 | e[2][NK] f32 | v[2][NK] f32 | s0[2] | red[2*NK]
#define OFF_E   (NT*NK)
#define OFF_V   (OFF_E + 2*NK*4)
#define OFF_S0  (OFF_V + 2*NK*4)
#define OFF_RED (OFF_S0 + 16)
#define SMEM_BYTES (OFF_RED + 2*NK*4)

__device__ __forceinline__ float ex2f(float x){ float y; asm("ex2.approx.ftz.f32 %0, %1;":"=f"(y):"f"(x)); return y; }
__device__ __forceinline__ float lg2f(float x){ float y; asm("lg2.approx.f32 %0, %1;":"=f"(y):"f"(x)); return y; }
__device__ __forceinline__ unsigned long long ffma2(unsigned long long a, unsigned long long b, unsigned long long c){
    unsigned long long d; asm("fma.rn.f32x2 %0, %1, %2, %3;" : "=l"(d) : "l"(a), "l"(b), "l"(c)); return d;
}

__global__ __launch_bounds__(128, 4)
void crf_kernel(const float* __restrict__ feats,
                const float* __restrict__ trans,
                float* __restrict__ out)
{
    extern __shared__ char smc[];
    unsigned char* bp = (unsigned char*)smc;
    float* eB  = (float*)(smc + OFF_E);    // exp2 of normalized log2-alpha, double-buffered
    float* vB  = (float*)(smc + OFF_V);    // viterbi values (plain domain), double-buffered
    float* s0B = (float*)(smc + OFF_S0);   // broadcast NORMALIZED A[0] (stable shift)
    float* red = (float*)(smc + OFF_RED);  // final reduction terms

    const int b   = blockIdx.x;
    const int tid = threadIdx.x;
    const bool isF = (tid < 64);           // warps 0-1: forward; warps 2-3: viterbi
    const int j   = isF ? tid : (tid - 64);
    const bool act = (j < NK);
    const float* f = feats + (size_t)b * NT * NK;

    union { unsigned long long e2[NK/2]; float tw[NK]; } u;   // E-row (fwd) XOR trans-row (vit)
    float A = 0.f, Csum = 0.f, vj = 0.f, featv = 0.f;

    if (act) {
        if (isF) {
            #pragma unroll
            for (int c = 0; c < NK/2; ++c) {
                float t0 = trans[j*NK + 2*c];
                float t1 = trans[j*NK + 2*c + 1];
                if (j == SSTART)   { t0 = NEGV; t1 = NEGV; }  // no transition into START row
                if (2*c   == SEND)   t0 = NEGV;               // no transition out of END col
                if (2*c+1 == SEND)   t1 = NEGV;
                float e0 = ex2f(t0 * L2E);                    // exact 0 for masked entries
                float e1 = ex2f(t1 * L2E);
                unsigned long long pk;
                asm("mov.b64 %0, {%1, %2};" : "=l"(pk) : "f"(e0), "f"(e1));
                u.e2[c] = pk;
            }
            A = (j == SSTART) ? 0.f : NEGV * L2E;
            eB[j] = (j == SSTART) ? 1.f : 0.f;                // e = exp2(A) initial
        } else {
            #pragma unroll
            for (int p = 0; p < NK; ++p) {
                float t = trans[j*NK + p];
                if (j == SSTART) t = NEGV;
                if (p == SEND)   t = NEGV;
                u.tw[p] = t;
            }
            vj = (j == SSTART) ? 0.f : NEGV;
            vB[j] = vj;
        }
        featv = __ldg(f + j);
    }
    if (tid == 0) s0B[0] = 0.f;
    __syncthreads();

    int cur = 0;
    #pragma unroll 1
    for (int t = 0; t < NT; ++t) {
        const int nxt = cur ^ 1;
        float featn = 0.f;
        if (act && t + 1 < NT) featn = __ldg(f + (t+1)*NK + j);   // prefetch

        if (act) {
            if (isF) {
                // forward: s_j = sum_p E[j][p] * e[p]  (packed f32x2 FFMA matvec)
                const ulonglong2* e2p = (const ulonglong2*)(eB + cur*NK);
                unsigned long long acc0 = 0ull, acc1 = 0ull;       // {+0,+0} packed
                #pragma unroll
                for (int c = 0; c < NK/4; ++c) {
                    ulonglong2 ev = e2p[c];                        // broadcast LDS.128
                    acc0 = ffma2(u.e2[2*c    ], ev.x, acc0);
                    acc1 = ffma2(u.e2[2*c + 1], ev.y, acc1);
                }
                float a0l, a0h, a1l, a1h;
                asm("mov.b64 {%0, %1}, %2;" : "=f"(a0l), "=f"(a0h) : "l"(acc0));
                asm("mov.b64 {%0, %1}, %2;" : "=f"(a1l), "=f"(a1h) : "l"(acc1));
                float s = (a0l + a0h) + (a1l + a1h);
                // STABLE shift: previous step's NORMALIZED A[0] (first-order damped,
                // A_{t+1}[j] = alpha2_{t+1}[j] - alpha2_t[0], bounded by one-step drift)
                float d = s0B[cur];
                d = fminf(fmaxf(d, -200.f), 200.f);   // defensive; algebra stays exact
                float raw = lg2f(s) + featv * L2E;    // alpha2_{t+1}[j] - C_t
                Csum += d;                            // C_{t+1} = C_t + d
                A = raw - d;                          // normalized log2-alpha
                eB[nxt*NK + j] = ex2f(A);
                if (j == 0) s0B[nxt] = A;             // <-- FIX: broadcast normalized value
            } else {
                // viterbi: plain float domain, identical op order to reference -> bit-exact
                const float4* v4 = (const float4*)(vB + cur*NK);
                float m0=-3.4e38f, m1=-3.4e38f, m2=-3.4e38f, m3=-3.4e38f;
                int   i0=0, i1=1, i2=2, i3=3;
                #pragma unroll
                for (int c = 0; c < NK/4; ++c) {
                    float4 vv = v4[c];                             // broadcast LDS.128
                    float y;
                    y = vv.x + u.tw[4*c+0]; if (y > m0) { m0=y; i0=4*c+0; }
                    y = vv.y + u.tw[4*c+1]; if (y > m1) { m1=y; i1=4*c+1; }
                    y = vv.z + u.tw[4*c+2]; if (y > m2) { m2=y; i2=4*c+2; }
                    y = vv.w + u.tw[4*c+3]; if (y > m3) { m3=y; i3=4*c+3; }
                }
                // merge with first-max tie-break (matches jnp.argmax)
                float bm = m0; int bi = i0;
                if (m1 > bm || (m1 == bm && i1 < bi)) { bm=m1; bi=i1; }
                if (m2 > bm || (m2 == bm && i2 < bi)) { bm=m2; bi=i2; }
                if (m3 > bm || (m3 == bm && i3 < bi)) { bm=m3; bi=i3; }
                vj = bm + featv;                    // emission added AFTER max (reference)
                bp[t*NK + j] = (unsigned char)bi;
                vB[nxt*NK + j] = vj;
            }
        }
        featv = featn;
        cur = nxt;
        __syncthreads();
    }

    // ---- termination ----
    if (act) {
        float te = trans[SEND*NK + j];
        if (j == SEND) te = NEGV;                   // column END masked
        if (isF) red[j]      = A  + te * L2E;       // log2 domain (C added at end)
        else     red[NK + j] = vj + te;             // plain, bit-exact
    }
    __syncthreads();

    if (tid == 0) {
        // logz = logsumexp(alpha + trans[END])
        float m = -3.4e38f;
        #pragma unroll
        for (int p = 0; p < NK; ++p) m = fmaxf(m, red[p]);
        float s = 0.f;
        #pragma unroll
        for (int p = 0; p < NK; ++p) s += ex2f(red[p] - m);
        out[b] = (m + lg2f(s) + Csum) * LN2F;
    }
    if (tid == 64) {
        // terminal first-max argmax + backtrace (runs concurrently with logz thread)
        float bm = -3.4e38f; int last = 0;
        #pragma unroll
        for (int p = 0; p < NK; ++p) {
            float y = red[NK + p];
            if (y > bm) { bm = y; last = p; }
        }
        out[NB + b] = bm;
        float* po = out + 2*NB + (size_t)b * NT;
        int tag = last;
        #pragma unroll 1
        for (int t = NT - 1; t >= 0; --t) {
            po[t] = (float)tag;
            tag = bp[t*NK + tag];
        }
    }
}

extern "C" void kernel_launch(void* const* d_in, const int* in_sizes, int n_in,
                              void* d_out, int out_size)
{
    const float* feats = (const float*)d_in[0];
    const float* trans = (const float*)d_in[1];
    float* out = (float*)d_out;
    cudaFuncSetAttribute(crf_kernel, cudaFuncAttributeMaxDynamicSharedMemorySize,
                         SMEM_BYTES);
    crf_kernel<<<NB, 128, SMEM_BYTES>>>(feats, trans, out);
}